// round 3
// baseline (speedup 1.0000x reference)
#include <cuda_runtime.h>

#define EPS_LN 1e-5f

// ---------------- scratch buffers (device globals; no allocs allowed) ----
__device__ float g_xT[67108864];      // [64][256][4096] LN(x) transposed, 256MB
__device__ float g_mqkT[256 * 256];   // B-matrix for q-projection: scale * Wq^T Wk (transposed)
__device__ float g_slots[512 * 256];
__device__ float g_sln[512 * 256];
__device__ float g_qt[512 * 256];
__device__ float g_attn[512 * 4096];  // logits -> attn weights, 8MB
__device__ float g_upd[512 * 256];
__device__ float g_updv[512 * 256];
__device__ float g_gi[512 * 768];
__device__ float g_gh[512 * 768];
__device__ float g_lnff[512 * 256];
__device__ float g_h1[512 * 256];

// ---------------- LN over x rows, write transposed ----------------------
// grid (128, 64), block 256.  Each block: 32 tokens of one batch.
__global__ void k_ln_big(const float* __restrict__ x,
                         const float* __restrict__ gam,
                         const float* __restrict__ bet)
{
    __shared__ float ts[32][257];
    int b = blockIdx.y;
    int n0 = blockIdx.x * 32;
    int wid = threadIdx.x >> 5, lane = threadIdx.x & 31;

#pragma unroll
    for (int j = 0; j < 4; j++) {
        int tok = wid * 4 + j;
        const float* row = x + ((size_t)b * 4096 + n0 + tok) * 256;
        float4 v0 = *(const float4*)(row + lane * 8);
        float4 v1 = *(const float4*)(row + lane * 8 + 4);
        float s  = v0.x + v0.y + v0.z + v0.w + v1.x + v1.y + v1.z + v1.w;
        float ss = v0.x*v0.x + v0.y*v0.y + v0.z*v0.z + v0.w*v0.w
                 + v1.x*v1.x + v1.y*v1.y + v1.z*v1.z + v1.w*v1.w;
#pragma unroll
        for (int o = 16; o; o >>= 1) {
            s  += __shfl_xor_sync(0xffffffffu, s,  o);
            ss += __shfl_xor_sync(0xffffffffu, ss, o);
        }
        float mu  = s * (1.0f / 256.0f);
        float var = ss * (1.0f / 256.0f) - mu * mu;
        float rs  = rsqrtf(var + EPS_LN);
        int d = lane * 8;
        float* tr = &ts[tok][0];
        tr[d+0] = (v0.x - mu) * rs * gam[d+0] + bet[d+0];
        tr[d+1] = (v0.y - mu) * rs * gam[d+1] + bet[d+1];
        tr[d+2] = (v0.z - mu) * rs * gam[d+2] + bet[d+2];
        tr[d+3] = (v0.w - mu) * rs * gam[d+3] + bet[d+3];
        tr[d+4] = (v1.x - mu) * rs * gam[d+4] + bet[d+4];
        tr[d+5] = (v1.y - mu) * rs * gam[d+5] + bet[d+5];
        tr[d+6] = (v1.z - mu) * rs * gam[d+6] + bet[d+6];
        tr[d+7] = (v1.w - mu) * rs * gam[d+7] + bet[d+7];
    }
    __syncthreads();
    float* outb = g_xT + (size_t)b * 256 * 4096;
#pragma unroll
    for (int dd = 0; dd < 32; dd++) {
        int d = wid * 32 + dd;
        outb[(size_t)d * 4096 + n0 + lane] = ts[lane][d];
    }
}

// ---------------- mqkT[d2][e] = scale * sum_c Wq[c][e] * Wk[c][d2] ------
__global__ void k_prep_mqk(const float* __restrict__ Wq, const float* __restrict__ Wk)
{
    int d2 = blockIdx.x, e = threadIdx.x;
    float acc = 0.f;
    for (int c = 0; c < 256; c++)
        acc += Wq[c * 256 + e] * Wk[c * 256 + d2];
    g_mqkT[d2 * 256 + e] = acc * 0.0625f;  // d^-0.5 = 1/16
}

// ---------------- slots init --------------------------------------------
__global__ void k_init_slots(const float* __restrict__ noise,
                             const float* __restrict__ mu,
                             const float* __restrict__ ls)
{
    int i = blockIdx.x * 256 + threadIdx.x;   // < 131072
    int d = i & 255;
    g_slots[i] = mu[d] + noise[i] * expf(ls[d]);
}

// ---------------- LN over 512 rows of 256 (warp per row) ----------------
__global__ void k_ln_small(const float* __restrict__ in, float* __restrict__ out,
                           const float* __restrict__ gam, const float* __restrict__ bet)
{
    int row  = blockIdx.x * 8 + (threadIdx.x >> 5);
    int lane = threadIdx.x & 31;
    const float* rp = in + row * 256;
    float4 v0 = *(const float4*)(rp + lane * 8);
    float4 v1 = *(const float4*)(rp + lane * 8 + 4);
    float s  = v0.x + v0.y + v0.z + v0.w + v1.x + v1.y + v1.z + v1.w;
    float ss = v0.x*v0.x + v0.y*v0.y + v0.z*v0.z + v0.w*v0.w
             + v1.x*v1.x + v1.y*v1.y + v1.z*v1.z + v1.w*v1.w;
#pragma unroll
    for (int o = 16; o; o >>= 1) {
        s  += __shfl_xor_sync(0xffffffffu, s,  o);
        ss += __shfl_xor_sync(0xffffffffu, ss, o);
    }
    float mu  = s * (1.0f / 256.0f);
    float var = ss * (1.0f / 256.0f) - mu * mu;
    float rs  = rsqrtf(var + EPS_LN);
    int d = lane * 8;
    float* op = out + row * 256;
    op[d+0] = (v0.x - mu) * rs * gam[d+0] + bet[d+0];
    op[d+1] = (v0.y - mu) * rs * gam[d+1] + bet[d+1];
    op[d+2] = (v0.z - mu) * rs * gam[d+2] + bet[d+2];
    op[d+3] = (v0.w - mu) * rs * gam[d+3] + bet[d+3];
    op[d+4] = (v1.x - mu) * rs * gam[d+4] + bet[d+4];
    op[d+5] = (v1.y - mu) * rs * gam[d+5] + bet[d+5];
    op[d+6] = (v1.z - mu) * rs * gam[d+6] + bet[d+6];
    op[d+7] = (v1.w - mu) * rs * gam[d+7] + bet[d+7];
}

// ---------------- generic NT GEMM: C[M][N] = A[M][256] * B[N][256]^T ----
// block tile 32x32, 256 threads, 2x2 per thread. flags: 1 = relu, 2 = C +=
__global__ void k_gemm(const float* __restrict__ A, const float* __restrict__ B,
                       const float* __restrict__ bias, float* __restrict__ C,
                       int N, int flags)
{
    __shared__ float As[32][33];
    __shared__ float Bs[32][33];
    int bm = blockIdx.y * 32, bn = blockIdx.x * 32;
    int tid = threadIdx.x;
    int tx = tid & 15, ty = tid >> 4;
    float a00 = 0.f, a01 = 0.f, a10 = 0.f, a11 = 0.f;

    int r  = tid >> 3;
    int c4 = (tid & 7) * 4;
    for (int k0 = 0; k0 < 256; k0 += 32) {
        float4 av = *(const float4*)(A + (size_t)(bm + r) * 256 + k0 + c4);
        As[r][c4+0] = av.x; As[r][c4+1] = av.y; As[r][c4+2] = av.z; As[r][c4+3] = av.w;
        float4 bv = *(const float4*)(B + (size_t)(bn + r) * 256 + k0 + c4);
        Bs[r][c4+0] = bv.x; Bs[r][c4+1] = bv.y; Bs[r][c4+2] = bv.z; Bs[r][c4+3] = bv.w;
        __syncthreads();
#pragma unroll
        for (int kk = 0; kk < 32; kk++) {
            float x0 = As[ty*2+0][kk], x1 = As[ty*2+1][kk];
            float y0 = Bs[tx*2+0][kk], y1 = Bs[tx*2+1][kk];
            a00 += x0 * y0; a01 += x0 * y1;
            a10 += x1 * y0; a11 += x1 * y1;
        }
        __syncthreads();
    }
    int m0 = bm + ty * 2, n0c = bn + tx * 2;
    float vals[2][2] = {{a00, a01}, {a10, a11}};
#pragma unroll
    for (int i = 0; i < 2; i++) {
#pragma unroll
        for (int j = 0; j < 2; j++) {
            float v = vals[i][j];
            if (bias) v += bias[n0c + j];
            size_t idx = (size_t)(m0 + i) * N + n0c + j;
            if (flags & 2) v += C[idx];
            if (flags & 1) v = fmaxf(v, 0.f);
            C[idx] = v;
        }
    }
}

// ---------------- logits: attn_raw[b][k][n] = sum_d qt[b][k][d]*xT[b][d][n]
// grid (4, 64), block 256; each thread: 4 tokens x 8 slots.
__global__ void k_logits()
{
    __shared__ float qst[256][8];
    int b = blockIdx.y, n0 = blockIdx.x * 1024;
    int tid = threadIdx.x;
    const float4* qsrc = (const float4*)(g_qt + b * 2048);
#pragma unroll
    for (int p = 0; p < 2; p++) {
        int q = tid + p * 256;            // float4 index 0..511
        float4 v = qsrc[q];
        int k = q >> 6;
        int d = (q & 63) * 4;
        qst[d+0][k] = v.x; qst[d+1][k] = v.y; qst[d+2][k] = v.z; qst[d+3][k] = v.w;
    }
    __syncthreads();

    const float* xr = g_xT + (size_t)b * (256 * 4096) + n0 + tid * 4;
    float4 acc[8];
#pragma unroll
    for (int k = 0; k < 8; k++) acc[k] = make_float4(0.f, 0.f, 0.f, 0.f);

    for (int d = 0; d < 256; d++) {
        float4 xv = *(const float4*)xr;
        xr += 4096;
        float4 q0 = *(const float4*)&qst[d][0];
        float4 q1 = *(const float4*)&qst[d][4];
        acc[0].x += q0.x*xv.x; acc[0].y += q0.x*xv.y; acc[0].z += q0.x*xv.z; acc[0].w += q0.x*xv.w;
        acc[1].x += q0.y*xv.x; acc[1].y += q0.y*xv.y; acc[1].z += q0.y*xv.z; acc[1].w += q0.y*xv.w;
        acc[2].x += q0.z*xv.x; acc[2].y += q0.z*xv.y; acc[2].z += q0.z*xv.z; acc[2].w += q0.z*xv.w;
        acc[3].x += q0.w*xv.x; acc[3].y += q0.w*xv.y; acc[3].z += q0.w*xv.z; acc[3].w += q0.w*xv.w;
        acc[4].x += q1.x*xv.x; acc[4].y += q1.x*xv.y; acc[4].z += q1.x*xv.z; acc[4].w += q1.x*xv.w;
        acc[5].x += q1.y*xv.x; acc[5].y += q1.y*xv.y; acc[5].z += q1.y*xv.z; acc[5].w += q1.y*xv.w;
        acc[6].x += q1.z*xv.x; acc[6].y += q1.z*xv.y; acc[6].z += q1.z*xv.z; acc[6].w += q1.z*xv.w;
        acc[7].x += q1.w*xv.x; acc[7].y += q1.w*xv.y; acc[7].z += q1.w*xv.z; acc[7].w += q1.w*xv.w;
    }
    float* ob = g_attn + (size_t)(b * 8) * 4096 + n0 + tid * 4;
#pragma unroll
    for (int k = 0; k < 8; k++)
        *(float4*)(ob + (size_t)k * 4096) = acc[k];
}

// ---------------- softmax + (p/S + 1e-8) / Z folded ---------------------
__global__ void k_softmax()
{
    __shared__ float red[8];
    int row = blockIdx.x;                 // 0..511 = (b*8+k)
    float* p = g_attn + (size_t)row * 4096;
    int tid = threadIdx.x;
    int wid = tid >> 5, lane = tid & 31;

    float4 v[4];
#pragma unroll
    for (int i = 0; i < 4; i++) v[i] = *(const float4*)(p + tid * 4 + i * 1024);

    float mx = -3.4e38f;
#pragma unroll
    for (int i = 0; i < 4; i++) {
        mx = fmaxf(mx, fmaxf(fmaxf(v[i].x, v[i].y), fmaxf(v[i].z, v[i].w)));
    }
#pragma unroll
    for (int o = 16; o; o >>= 1) mx = fmaxf(mx, __shfl_xor_sync(0xffffffffu, mx, o));
    if (lane == 0) red[wid] = mx;
    __syncthreads();
    mx = red[0];
#pragma unroll
    for (int i = 1; i < 8; i++) mx = fmaxf(mx, red[i]);
    __syncthreads();

    float s = 0.f;
#pragma unroll
    for (int i = 0; i < 4; i++) {
        v[i].x = expf(v[i].x - mx); v[i].y = expf(v[i].y - mx);
        v[i].z = expf(v[i].z - mx); v[i].w = expf(v[i].w - mx);
        s += v[i].x + v[i].y + v[i].z + v[i].w;
    }
#pragma unroll
    for (int o = 16; o; o >>= 1) s += __shfl_xor_sync(0xffffffffu, s, o);
    if (lane == 0) red[wid] = s;
    __syncthreads();
    s = red[0];
#pragma unroll
    for (int i = 1; i < 8; i++) s += red[i];

    const float Z   = 1.0f + 4096.0f * 1e-8f;
    float inv = 1.0f / (s * Z);
    float c   = 1e-8f / Z;
#pragma unroll
    for (int i = 0; i < 4; i++) {
        float4 o4;
        o4.x = v[i].x * inv + c; o4.y = v[i].y * inv + c;
        o4.z = v[i].z * inv + c; o4.w = v[i].w * inv + c;
        *(float4*)(p + tid * 4 + i * 1024) = o4;
    }
}

__global__ void k_zero_upd()
{
    g_upd[blockIdx.x * 256 + threadIdx.x] = 0.f;
}

// ---------------- u'[b][k][d] = sum_n attn[b][k][n] * xT[b][d][n] -------
// grid (4, 64), block 256 (thread = d), partial over 1024 tokens, atomics.
__global__ void k_uprime()
{
    __shared__ float ps[8][1024];         // 32KB
    int b = blockIdx.y, n0 = blockIdx.x * 1024, tid = threadIdx.x;
#pragma unroll
    for (int p = 0; p < 8; p++) {
        int q  = tid + p * 256;           // float4 index 0..2047
        int k  = q >> 8;
        int c4 = (q & 255) * 4;
        *(float4*)&ps[k][c4] =
            *(const float4*)(g_attn + (size_t)(b * 8 + k) * 4096 + n0 + c4);
    }
    __syncthreads();

    const float* xp = g_xT + (size_t)b * (256 * 4096) + (size_t)tid * 4096 + n0;
    float acc[8] = {0.f, 0.f, 0.f, 0.f, 0.f, 0.f, 0.f, 0.f};
    for (int n = 0; n < 1024; n += 4) {
        float4 xv = *(const float4*)(xp + n);
#pragma unroll
        for (int k = 0; k < 8; k++) {
            float4 pv = *(const float4*)&ps[k][n];
            acc[k] += pv.x * xv.x + pv.y * xv.y + pv.z * xv.z + pv.w * xv.w;
        }
    }
#pragma unroll
    for (int k = 0; k < 8; k++)
        atomicAdd(&g_upd[(b * 8 + k) * 256 + tid], acc[k]);
}

// ---------------- GRU gates (gi, gh have bias already added) ------------
__global__ void k_gate()
{
    int i = blockIdx.x * 256 + threadIdx.x;  // < 131072
    int row = i >> 8, d = i & 255;
    const float* gi = g_gi + row * 768;
    const float* gh = g_gh + row * 768;
    float ir = gi[d], iz = gi[256 + d], in_ = gi[512 + d];
    float hr = gh[d], hz = gh[256 + d], hn  = gh[512 + d];
    float rr = 1.0f / (1.0f + expf(-(ir + hr)));
    float zz = 1.0f / (1.0f + expf(-(iz + hz)));
    float nn = tanhf(in_ + rr * hn);
    float h  = g_slots[i];
    g_slots[i] = (1.0f - zz) * nn + zz * h;
}

__global__ void k_copy_out(float* __restrict__ out)
{
    int i = blockIdx.x * 256 + threadIdx.x;
    out[i] = g_slots[i];
}

// ---------------- launcher ----------------------------------------------
extern "C" void kernel_launch(void* const* d_in, const int* in_sizes, int n_in,
                              void* d_out, int out_size)
{
    const float* x     = (const float*)d_in[0];
    const float* noise = (const float*)d_in[1];
    const float* mu    = (const float*)d_in[2];
    const float* ls    = (const float*)d_in[3];
    const float* Wq    = (const float*)d_in[4];
    const float* Wk    = (const float*)d_in[5];
    const float* Wv    = (const float*)d_in[6];
    const float* W_ih  = (const float*)d_in[7];
    const float* W_hh  = (const float*)d_in[8];
    const float* b_ih  = (const float*)d_in[9];
    const float* b_hh  = (const float*)d_in[10];
    const float* W1    = (const float*)d_in[11];
    const float* b1    = (const float*)d_in[12];
    const float* W2    = (const float*)d_in[13];
    const float* b2    = (const float*)d_in[14];
    const float* gin   = (const float*)d_in[15];
    const float* bein  = (const float*)d_in[16];
    const float* gsl   = (const float*)d_in[17];
    const float* besl  = (const float*)d_in[18];
    const float* gff   = (const float*)d_in[19];
    const float* beff  = (const float*)d_in[20];
    float* out = (float*)d_out;

    float *p_slots, *p_sln, *p_qt, *p_upd, *p_updv, *p_gi, *p_gh, *p_lnff, *p_h1, *p_mqkT;
    cudaGetSymbolAddress((void**)&p_slots, g_slots);
    cudaGetSymbolAddress((void**)&p_sln,   g_sln);
    cudaGetSymbolAddress((void**)&p_qt,    g_qt);
    cudaGetSymbolAddress((void**)&p_upd,   g_upd);
    cudaGetSymbolAddress((void**)&p_updv,  g_updv);
    cudaGetSymbolAddress((void**)&p_gi,    g_gi);
    cudaGetSymbolAddress((void**)&p_gh,    g_gh);
    cudaGetSymbolAddress((void**)&p_lnff,  g_lnff);
    cudaGetSymbolAddress((void**)&p_h1,    g_h1);
    cudaGetSymbolAddress((void**)&p_mqkT,  g_mqkT);

    k_ln_big<<<dim3(128, 64), 256>>>(x, gin, bein);
    k_prep_mqk<<<256, 256>>>(Wq, Wk);
    k_init_slots<<<512, 256>>>(noise, mu, ls);

    for (int it = 0; it < 3; it++) {
        // q-projection (LN_sl folded + combined Wq^T Wk matrix, scale included)
        k_ln_small<<<64, 256>>>(p_slots, p_sln, gsl, besl);
        k_gemm<<<dim3(8, 16), 256>>>(p_sln, p_mqkT, nullptr, p_qt, 256, 0);

        // attention over tokens
        k_logits<<<dim3(4, 64), 256>>>();
        k_softmax<<<512, 256>>>();
        k_zero_upd<<<512, 256>>>();
        k_uprime<<<dim3(4, 64), 256>>>();
        k_gemm<<<dim3(8, 16), 256>>>(p_upd, Wv, nullptr, p_updv, 256, 0);

        // GRU
        k_gemm<<<dim3(24, 16), 256>>>(p_updv, W_ih, b_ih, p_gi, 768, 0);
        k_gemm<<<dim3(24, 16), 256>>>(p_slots, W_hh, b_hh, p_gh, 768, 0);
        k_gate<<<512, 256>>>();

        // FF residual
        k_ln_small<<<64, 256>>>(p_slots, p_lnff, gff, beff);
        k_gemm<<<dim3(8, 16), 256>>>(p_lnff, W1, b1, p_h1, 256, 1);
        k_gemm<<<dim3(8, 16), 256>>>(p_h1, W2, b2, p_slots, 256, 2);
    }

    k_copy_out<<<512, 256>>>(out);
}

// round 5
// speedup vs baseline: 1.3045x; 1.3045x over previous
#include <cuda_runtime.h>

#define EPS_LN 1e-5f

// ---------------- scratch buffers (device globals; no allocs allowed) ----
__device__ float g_xT[67108864];      // [64][256][4096] LN(x) transposed, 256MB
__device__ float g_xln[67108864];     // [64][4096][256] LN(x) row-major, 256MB
__device__ float g_mqkT[256 * 256];   // scale * Wq^T Wk (transposed)
__device__ float g_slots[512 * 256];
__device__ float g_sln[512 * 256];
__device__ float g_qt[512 * 256];
__device__ float g_attn[512 * 4096];  // logits -> attn weights, 8MB
__device__ float g_upd[512 * 256];
__device__ float g_updv[512 * 256];
__device__ float g_gi[512 * 768];
__device__ float g_gh[512 * 768];
__device__ float g_lnff[512 * 256];
__device__ float g_h1[512 * 256];

// ---------------- LN over x rows, write BOTH layouts --------------------
// grid (128, 64), block 256.  Each block: 32 tokens of one batch.
__global__ void k_ln_big(const float* __restrict__ x,
                         const float* __restrict__ gam,
                         const float* __restrict__ bet)
{
    __shared__ float ts[32][257];     // scalar access only (row stride not 16B-mult)
    int b = blockIdx.y;
    int n0 = blockIdx.x * 32;
    int wid = threadIdx.x >> 5, lane = threadIdx.x & 31;

#pragma unroll
    for (int j = 0; j < 4; j++) {
        int tok = wid * 4 + j;
        const float* row = x + ((size_t)b * 4096 + n0 + tok) * 256;
        float4 v0 = *(const float4*)(row + lane * 8);
        float4 v1 = *(const float4*)(row + lane * 8 + 4);
        float s  = v0.x + v0.y + v0.z + v0.w + v1.x + v1.y + v1.z + v1.w;
        float ss = v0.x*v0.x + v0.y*v0.y + v0.z*v0.z + v0.w*v0.w
                 + v1.x*v1.x + v1.y*v1.y + v1.z*v1.z + v1.w*v1.w;
#pragma unroll
        for (int o = 16; o; o >>= 1) {
            s  += __shfl_xor_sync(0xffffffffu, s,  o);
            ss += __shfl_xor_sync(0xffffffffu, ss, o);
        }
        float mu  = s * (1.0f / 256.0f);
        float var = ss * (1.0f / 256.0f) - mu * mu;
        float rs  = rsqrtf(var + EPS_LN);
        int d = lane * 8;
        float4 o0, o1;
        o0.x = (v0.x - mu) * rs * gam[d+0] + bet[d+0];
        o0.y = (v0.y - mu) * rs * gam[d+1] + bet[d+1];
        o0.z = (v0.z - mu) * rs * gam[d+2] + bet[d+2];
        o0.w = (v0.w - mu) * rs * gam[d+3] + bet[d+3];
        o1.x = (v1.x - mu) * rs * gam[d+4] + bet[d+4];
        o1.y = (v1.y - mu) * rs * gam[d+5] + bet[d+5];
        o1.z = (v1.z - mu) * rs * gam[d+6] + bet[d+6];
        o1.w = (v1.w - mu) * rs * gam[d+7] + bet[d+7];
        // scalar stores into padded smem (misaligned-safe)
        float* tr = &ts[tok][0];
        tr[d+0] = o0.x; tr[d+1] = o0.y; tr[d+2] = o0.z; tr[d+3] = o0.w;
        tr[d+4] = o1.x; tr[d+5] = o1.y; tr[d+6] = o1.z; tr[d+7] = o1.w;
        // row-major copy to gmem (16B-aligned: d multiple of 8 floats)
        float* xr = g_xln + ((size_t)b * 4096 + n0 + tok) * 256 + d;
        *(float4*)(xr)     = o0;
        *(float4*)(xr + 4) = o1;
    }
    __syncthreads();
    float* outb = g_xT + (size_t)b * 256 * 4096;
#pragma unroll
    for (int dd = 0; dd < 32; dd++) {
        int d = wid * 32 + dd;
        outb[(size_t)d * 4096 + n0 + lane] = ts[lane][d];
    }
}

// ---------------- mqkT[d2][e] = scale * sum_c Wq[c][e] * Wk[c][d2] ------
__global__ void k_prep_mqk(const float* __restrict__ Wq, const float* __restrict__ Wk)
{
    int d2 = blockIdx.x, e = threadIdx.x;
    float acc = 0.f;
    for (int c = 0; c < 256; c++)
        acc += Wq[c * 256 + e] * Wk[c * 256 + d2];
    g_mqkT[d2 * 256 + e] = acc * 0.0625f;  // d^-0.5 = 1/16
}

// ---------------- slots init --------------------------------------------
__global__ void k_init_slots(const float* __restrict__ noise,
                             const float* __restrict__ mu,
                             const float* __restrict__ ls)
{
    int i = blockIdx.x * 256 + threadIdx.x;   // < 131072
    int d = i & 255;
    g_slots[i] = mu[d] + noise[i] * expf(ls[d]);
}

// ---------------- LN over 512 rows of 256 (warp per row) ----------------
__global__ void k_ln_small(const float* __restrict__ in, float* __restrict__ out,
                           const float* __restrict__ gam, const float* __restrict__ bet)
{
    int row  = blockIdx.x * 8 + (threadIdx.x >> 5);
    int lane = threadIdx.x & 31;
    const float* rp = in + row * 256;
    float4 v0 = *(const float4*)(rp + lane * 8);
    float4 v1 = *(const float4*)(rp + lane * 8 + 4);
    float s  = v0.x + v0.y + v0.z + v0.w + v1.x + v1.y + v1.z + v1.w;
    float ss = v0.x*v0.x + v0.y*v0.y + v0.z*v0.z + v0.w*v0.w
             + v1.x*v1.x + v1.y*v1.y + v1.z*v1.z + v1.w*v1.w;
#pragma unroll
    for (int o = 16; o; o >>= 1) {
        s  += __shfl_xor_sync(0xffffffffu, s,  o);
        ss += __shfl_xor_sync(0xffffffffu, ss, o);
    }
    float mu  = s * (1.0f / 256.0f);
    float var = ss * (1.0f / 256.0f) - mu * mu;
    float rs  = rsqrtf(var + EPS_LN);
    int d = lane * 8;
    float* op = out + row * 256;
    op[d+0] = (v0.x - mu) * rs * gam[d+0] + bet[d+0];
    op[d+1] = (v0.y - mu) * rs * gam[d+1] + bet[d+1];
    op[d+2] = (v0.z - mu) * rs * gam[d+2] + bet[d+2];
    op[d+3] = (v0.w - mu) * rs * gam[d+3] + bet[d+3];
    op[d+4] = (v1.x - mu) * rs * gam[d+4] + bet[d+4];
    op[d+5] = (v1.y - mu) * rs * gam[d+5] + bet[d+5];
    op[d+6] = (v1.z - mu) * rs * gam[d+6] + bet[d+6];
    op[d+7] = (v1.w - mu) * rs * gam[d+7] + bet[d+7];
}

// ---------------- generic NT GEMM 32x32: C = A[M][256] * B[N][256]^T ----
// flags: 1 = relu, 2 = C +=
__global__ void k_gemm(const float* __restrict__ A, const float* __restrict__ B,
                       const float* __restrict__ bias, float* __restrict__ C,
                       int N, int flags)
{
    __shared__ float As[32][33];
    __shared__ float Bs[32][33];
    int bm = blockIdx.y * 32, bn = blockIdx.x * 32;
    int tid = threadIdx.x;
    int tx = tid & 15, ty = tid >> 4;
    float a00 = 0.f, a01 = 0.f, a10 = 0.f, a11 = 0.f;

    int r  = tid >> 3;
    int c4 = (tid & 7) * 4;
    for (int k0 = 0; k0 < 256; k0 += 32) {
        float4 av = *(const float4*)(A + (size_t)(bm + r) * 256 + k0 + c4);
        As[r][c4+0] = av.x; As[r][c4+1] = av.y; As[r][c4+2] = av.z; As[r][c4+3] = av.w;
        float4 bv = *(const float4*)(B + (size_t)(bn + r) * 256 + k0 + c4);
        Bs[r][c4+0] = bv.x; Bs[r][c4+1] = bv.y; Bs[r][c4+2] = bv.z; Bs[r][c4+3] = bv.w;
        __syncthreads();
#pragma unroll
        for (int kk = 0; kk < 32; kk++) {
            float x0 = As[ty*2+0][kk], x1 = As[ty*2+1][kk];
            float y0 = Bs[tx*2+0][kk], y1 = Bs[tx*2+1][kk];
            a00 += x0 * y0; a01 += x0 * y1;
            a10 += x1 * y0; a11 += x1 * y1;
        }
        __syncthreads();
    }
    int m0 = bm + ty * 2, n0c = bn + tx * 2;
    float vals[2][2] = {{a00, a01}, {a10, a11}};
#pragma unroll
    for (int i = 0; i < 2; i++) {
#pragma unroll
        for (int j = 0; j < 2; j++) {
            float v = vals[i][j];
            if (bias) v += bias[n0c + j];
            size_t idx = (size_t)(m0 + i) * N + n0c + j;
            if (flags & 2) v += C[idx];
            if (flags & 1) v = fmaxf(v, 0.f);
            C[idx] = v;
        }
    }
}

// ---------------- 64x64-tile NT GEMM (for the 768-wide GRU gemms) -------
// Row stride 72 floats = 288B (16B multiple) + __align__(16) => float4-safe.
__global__ void k_gemm64(const float* __restrict__ A, const float* __restrict__ B,
                         const float* __restrict__ bias, float* __restrict__ C,
                         int N, int flags)
{
    __shared__ __align__(16) float As[16][72];
    __shared__ __align__(16) float Bs[16][72];
    int bm = blockIdx.y * 64, bn = blockIdx.x * 64;
    int tid = threadIdx.x;
    int tx = tid & 15, ty = tid >> 4;     // 4x4 micro-tile coords
    int lm = tid >> 2;                    // 0..63
    int lk = (tid & 3) * 4;               // 0,4,8,12
    float acc[4][4] = {};

    for (int k0 = 0; k0 < 256; k0 += 16) {
        float4 av = *(const float4*)(A + (size_t)(bm + lm) * 256 + k0 + lk);
        float4 bv = *(const float4*)(B + (size_t)(bn + lm) * 256 + k0 + lk);
        __syncthreads();
        As[lk+0][lm] = av.x; As[lk+1][lm] = av.y; As[lk+2][lm] = av.z; As[lk+3][lm] = av.w;
        Bs[lk+0][lm] = bv.x; Bs[lk+1][lm] = bv.y; Bs[lk+2][lm] = bv.z; Bs[lk+3][lm] = bv.w;
        __syncthreads();
#pragma unroll
        for (int kk = 0; kk < 16; kk++) {
            float4 a = *(const float4*)&As[kk][ty * 4];
            float4 b = *(const float4*)&Bs[kk][tx * 4];
            acc[0][0] += a.x*b.x; acc[0][1] += a.x*b.y; acc[0][2] += a.x*b.z; acc[0][3] += a.x*b.w;
            acc[1][0] += a.y*b.x; acc[1][1] += a.y*b.y; acc[1][2] += a.y*b.z; acc[1][3] += a.y*b.w;
            acc[2][0] += a.z*b.x; acc[2][1] += a.z*b.y; acc[2][2] += a.z*b.z; acc[2][3] += a.z*b.w;
            acc[3][0] += a.w*b.x; acc[3][1] += a.w*b.y; acc[3][2] += a.w*b.z; acc[3][3] += a.w*b.w;
        }
    }
#pragma unroll
    for (int i = 0; i < 4; i++) {
#pragma unroll
        for (int j = 0; j < 4; j++) {
            int m = bm + ty * 4 + i, n = bn + tx * 4 + j;
            float v = acc[i][j];
            if (bias) v += bias[n];
            size_t idx = (size_t)m * N + n;
            if (flags & 2) v += C[idx];
            if (flags & 1) v = fmaxf(v, 0.f);
            C[idx] = v;
        }
    }
}

// ---------------- logits: attn_raw[b][k][n] = sum_d qt[b][k][d]*xT[b][d][n]
// grid (4, 64), block 256; each thread: 4 tokens x 8 slots.
__global__ void k_logits()
{
    __shared__ __align__(16) float qst[256][8];   // row = 32B: float4-safe
    int b = blockIdx.y, n0 = blockIdx.x * 1024;
    int tid = threadIdx.x;
    const float4* qsrc = (const float4*)(g_qt + b * 2048);
#pragma unroll
    for (int p = 0; p < 2; p++) {
        int q = tid + p * 256;            // float4 index 0..511
        float4 v = qsrc[q];
        int k = q >> 6;
        int d = (q & 63) * 4;
        qst[d+0][k] = v.x; qst[d+1][k] = v.y; qst[d+2][k] = v.z; qst[d+3][k] = v.w;
    }
    __syncthreads();

    const float* xr = g_xT + (size_t)b * (256 * 4096) + n0 + tid * 4;
    float4 acc[8];
#pragma unroll
    for (int k = 0; k < 8; k++) acc[k] = make_float4(0.f, 0.f, 0.f, 0.f);

    for (int d = 0; d < 256; d++) {
        float4 xv = *(const float4*)xr;
        xr += 4096;
        float4 q0 = *(const float4*)&qst[d][0];
        float4 q1 = *(const float4*)&qst[d][4];
        acc[0].x += q0.x*xv.x; acc[0].y += q0.x*xv.y; acc[0].z += q0.x*xv.z; acc[0].w += q0.x*xv.w;
        acc[1].x += q0.y*xv.x; acc[1].y += q0.y*xv.y; acc[1].z += q0.y*xv.z; acc[1].w += q0.y*xv.w;
        acc[2].x += q0.z*xv.x; acc[2].y += q0.z*xv.y; acc[2].z += q0.z*xv.z; acc[2].w += q0.z*xv.w;
        acc[3].x += q0.w*xv.x; acc[3].y += q0.w*xv.y; acc[3].z += q0.w*xv.z; acc[3].w += q0.w*xv.w;
        acc[4].x += q1.x*xv.x; acc[4].y += q1.x*xv.y; acc[4].z += q1.x*xv.z; acc[4].w += q1.x*xv.w;
        acc[5].x += q1.y*xv.x; acc[5].y += q1.y*xv.y; acc[5].z += q1.y*xv.z; acc[5].w += q1.y*xv.w;
        acc[6].x += q1.z*xv.x; acc[6].y += q1.z*xv.y; acc[6].z += q1.z*xv.z; acc[6].w += q1.z*xv.w;
        acc[7].x += q1.w*xv.x; acc[7].y += q1.w*xv.y; acc[7].z += q1.w*xv.z; acc[7].w += q1.w*xv.w;
    }
    float* ob = g_attn + (size_t)(b * 8) * 4096 + n0 + tid * 4;
#pragma unroll
    for (int k = 0; k < 8; k++)
        *(float4*)(ob + (size_t)k * 4096) = acc[k];
}

// ---------------- softmax + (p/S + 1e-8)/Z folded + zero g_upd ----------
__global__ void k_softmax()
{
    __shared__ float red[8];
    int row = blockIdx.x;                 // 0..511 = (b*8+k)
    float* p = g_attn + (size_t)row * 4096;
    int tid = threadIdx.x;
    int wid = tid >> 5, lane = tid & 31;

    g_upd[row * 256 + tid] = 0.f;         // zero updates buffer for uprime atomics

    float4 v[4];
#pragma unroll
    for (int i = 0; i < 4; i++) v[i] = *(const float4*)(p + tid * 4 + i * 1024);

    float mx = -3.4e38f;
#pragma unroll
    for (int i = 0; i < 4; i++) {
        mx = fmaxf(mx, fmaxf(fmaxf(v[i].x, v[i].y), fmaxf(v[i].z, v[i].w)));
    }
#pragma unroll
    for (int o = 16; o; o >>= 1) mx = fmaxf(mx, __shfl_xor_sync(0xffffffffu, mx, o));
    if (lane == 0) red[wid] = mx;
    __syncthreads();
    mx = red[0];
#pragma unroll
    for (int i = 1; i < 8; i++) mx = fmaxf(mx, red[i]);
    __syncthreads();

    float s = 0.f;
#pragma unroll
    for (int i = 0; i < 4; i++) {
        v[i].x = expf(v[i].x - mx); v[i].y = expf(v[i].y - mx);
        v[i].z = expf(v[i].z - mx); v[i].w = expf(v[i].w - mx);
        s += v[i].x + v[i].y + v[i].z + v[i].w;
    }
#pragma unroll
    for (int o = 16; o; o >>= 1) s += __shfl_xor_sync(0xffffffffu, s, o);
    if (lane == 0) red[wid] = s;
    __syncthreads();
    s = red[0];
#pragma unroll
    for (int i = 1; i < 8; i++) s += red[i];

    const float Z   = 1.0f + 4096.0f * 1e-8f;
    float inv = 1.0f / (s * Z);
    float c   = 1e-8f / Z;
#pragma unroll
    for (int i = 0; i < 4; i++) {
        float4 o4;
        o4.x = v[i].x * inv + c; o4.y = v[i].y * inv + c;
        o4.z = v[i].z * inv + c; o4.w = v[i].w * inv + c;
        *(float4*)(p + tid * 4 + i * 1024) = o4;
    }
}

// ---------------- u'[b][k][d] = sum_n attn[b][k][n] * xln[b][n][d] ------
// grid (8, 64), block 128. chunk = 512 tokens. COALESCED over d.
__global__ void k_uprime()
{
    __shared__ __align__(16) float ps[8][512];   // 16KB attn chunk (row = 2KB: float4-safe)
    __shared__ float red[64][33];                // cross-group reduce (scalar access)
    int b = blockIdx.y, n0 = blockIdx.x * 512, tid = threadIdx.x;

#pragma unroll
    for (int p = 0; p < 8; p++) {
        int q  = tid + p * 128;           // float4 index 0..1023
        int k  = q >> 7;
        int c4 = (q & 127) * 4;
        *(float4*)&ps[k][c4] =
            *(const float4*)(g_attn + (size_t)(b * 8 + k) * 4096 + n0 + c4);
    }
    __syncthreads();

    int g  = tid >> 6;                    // token parity group 0/1
    int dl = tid & 63;
    int d4 = dl * 4;
    float4 acc[8];
#pragma unroll
    for (int k = 0; k < 8; k++) acc[k] = make_float4(0.f, 0.f, 0.f, 0.f);

    const float* xb = g_xln + ((size_t)b * 4096 + n0) * 256 + d4;
#pragma unroll 4
    for (int i = 0; i < 256; i++) {
        int n = g + i * 2;
        float4 xv = *(const float4*)(xb + (size_t)n * 256);
#pragma unroll
        for (int k = 0; k < 8; k++) {
            float pv = ps[k][n];
            acc[k].x += pv * xv.x; acc[k].y += pv * xv.y;
            acc[k].z += pv * xv.z; acc[k].w += pv * xv.w;
        }
    }

    if (g == 1) {
#pragma unroll
        for (int k = 0; k < 8; k++) {
            red[dl][k*4+0] = acc[k].x; red[dl][k*4+1] = acc[k].y;
            red[dl][k*4+2] = acc[k].z; red[dl][k*4+3] = acc[k].w;
        }
    }
    __syncthreads();
    if (g == 0) {
#pragma unroll
        for (int k = 0; k < 8; k++) {
            float* dst = g_upd + (size_t)(b * 8 + k) * 256 + d4;
            atomicAdd(dst + 0, acc[k].x + red[dl][k*4+0]);
            atomicAdd(dst + 1, acc[k].y + red[dl][k*4+1]);
            atomicAdd(dst + 2, acc[k].z + red[dl][k*4+2]);
            atomicAdd(dst + 3, acc[k].w + red[dl][k*4+3]);
        }
    }
}

// ---------------- GRU gates (gi, gh have bias already added) ------------
__global__ void k_gate()
{
    int i = blockIdx.x * 256 + threadIdx.x;  // < 131072
    int row = i >> 8, d = i & 255;
    const float* gi = g_gi + row * 768;
    const float* gh = g_gh + row * 768;
    float ir = gi[d], iz = gi[256 + d], in_ = gi[512 + d];
    float hr = gh[d], hz = gh[256 + d], hn  = gh[512 + d];
    float rr = 1.0f / (1.0f + expf(-(ir + hr)));
    float zz = 1.0f / (1.0f + expf(-(iz + hz)));
    float nn = tanhf(in_ + rr * hn);
    float h  = g_slots[i];
    g_slots[i] = (1.0f - zz) * nn + zz * h;
}

__global__ void k_copy_out(float* __restrict__ out)
{
    int i = blockIdx.x * 256 + threadIdx.x;
    out[i] = g_slots[i];
}

// ---------------- launcher ----------------------------------------------
extern "C" void kernel_launch(void* const* d_in, const int* in_sizes, int n_in,
                              void* d_out, int out_size)
{
    const float* x     = (const float*)d_in[0];
    const float* noise = (const float*)d_in[1];
    const float* mu    = (const float*)d_in[2];
    const float* ls    = (const float*)d_in[3];
    const float* Wq    = (const float*)d_in[4];
    const float* Wk    = (const float*)d_in[5];
    const float* Wv    = (const float*)d_in[6];
    const float* W_ih  = (const float*)d_in[7];
    const float* W_hh  = (const float*)d_in[8];
    const float* b_ih  = (const float*)d_in[9];
    const float* b_hh  = (const float*)d_in[10];
    const float* W1    = (const float*)d_in[11];
    const float* b1    = (const float*)d_in[12];
    const float* W2    = (const float*)d_in[13];
    const float* b2    = (const float*)d_in[14];
    const float* gin   = (const float*)d_in[15];
    const float* bein  = (const float*)d_in[16];
    const float* gsl   = (const float*)d_in[17];
    const float* besl  = (const float*)d_in[18];
    const float* gff   = (const float*)d_in[19];
    const float* beff  = (const float*)d_in[20];
    float* out = (float*)d_out;

    float *p_slots, *p_sln, *p_qt, *p_upd, *p_updv, *p_gi, *p_gh, *p_lnff, *p_h1, *p_mqkT;
    cudaGetSymbolAddress((void**)&p_slots, g_slots);
    cudaGetSymbolAddress((void**)&p_sln,   g_sln);
    cudaGetSymbolAddress((void**)&p_qt,    g_qt);
    cudaGetSymbolAddress((void**)&p_upd,   g_upd);
    cudaGetSymbolAddress((void**)&p_updv,  g_updv);
    cudaGetSymbolAddress((void**)&p_gi,    g_gi);
    cudaGetSymbolAddress((void**)&p_gh,    g_gh);
    cudaGetSymbolAddress((void**)&p_lnff,  g_lnff);
    cudaGetSymbolAddress((void**)&p_h1,    g_h1);
    cudaGetSymbolAddress((void**)&p_mqkT,  g_mqkT);

    k_ln_big<<<dim3(128, 64), 256>>>(x, gin, bein);
    k_prep_mqk<<<256, 256>>>(Wq, Wk);
    k_init_slots<<<512, 256>>>(noise, mu, ls);

    for (int it = 0; it < 3; it++) {
        // q-projection (LN_sl folded + combined Wq^T Wk matrix, scale included)
        k_ln_small<<<64, 256>>>(p_slots, p_sln, gsl, besl);
        k_gemm<<<dim3(8, 16), 256>>>(p_sln, p_mqkT, nullptr, p_qt, 256, 0);

        // attention over tokens
        k_logits<<<dim3(4, 64), 256>>>();
        k_softmax<<<512, 256>>>();
        k_uprime<<<dim3(8, 64), 128>>>();
        k_gemm<<<dim3(8, 16), 256>>>(p_upd, Wv, nullptr, p_updv, 256, 0);

        // GRU
        k_gemm64<<<dim3(12, 8), 256>>>(p_updv, W_ih, b_ih, p_gi, 768, 0);
        k_gemm64<<<dim3(12, 8), 256>>>(p_slots, W_hh, b_hh, p_gh, 768, 0);
        k_gate<<<512, 256>>>();

        // FF residual
        k_ln_small<<<64, 256>>>(p_slots, p_lnff, gff, beff);
        k_gemm<<<dim3(8, 16), 256>>>(p_lnff, W1, b1, p_h1, 256, 1);
        k_gemm<<<dim3(8, 16), 256>>>(p_h1, W2, b2, p_slots, 256, 2);
    }

    k_copy_out<<<512, 256>>>(out);
}